// round 1
// baseline (speedup 1.0000x reference)
#include <cuda_runtime.h>

// Problem constants (fixed shapes from reference):
//   x      : (4, 64, 768)  fp32   -> A [256 x 768]
//   scale  : (1, 8, 768)   fp32
//   binary : (1, 8, 96, 768) int32 (byte values 0..255, packed sign bits)
//   bias   : (768,)        fp32
//   out    : (4, 64, 768)  fp32   -> C [256 x 768]
//
// out[b,f] = sum_j x[b,j] * Weff[j,f] + bias[f]
// Weff[8m+p, f] = sum_k scale[k,f] * ( bit(7-p, binary[k,m,f]) ? +1 : -1 )

#define NX 768       // input features (K)
#define NF 768       // output features (N)
#define NBROWS 256   // batch rows (M) = 4*64
#define BITS 8
#define NG 96        // NX / 8 groups

// Scratch for the folded weight matrix (device global: allocation-free).
__device__ float g_weff[NX * NF];

// ---------------------------------------------------------------------------
// Kernel 1: fold 8 bit-planes * scale into a single fp32 weight matrix.
// One thread per (group m, output feature f): produces 8 weights (p=0..7).
// ---------------------------------------------------------------------------
__global__ __launch_bounds__(256)
void build_weff_kernel(const float* __restrict__ scale,
                       const int*   __restrict__ binary) {
    int t = blockIdx.x * 256 + threadIdx.x;
    if (t >= NG * NF) return;
    int f = t % NF;          // contiguous across threads -> coalesced
    int m = t / NF;

    float w[8];
#pragma unroll
    for (int p = 0; p < 8; p++) w[p] = 0.0f;

#pragma unroll
    for (int k = 0; k < BITS; k++) {
        int   c = binary[(k * NG + m) * NF + f];
        float s = scale[k * NF + f];
#pragma unroll
        for (int p = 0; p < 8; p++) {
            w[p] += ((c >> (7 - p)) & 1) ? s : -s;
        }
    }
#pragma unroll
    for (int p = 0; p < 8; p++) {
        g_weff[(m * 8 + p) * NF + f] = w[p];   // coalesced across f
    }
}

// ---------------------------------------------------------------------------
// Kernel 2: fp32 GEMM  C[256x768] = A[256x768] @ Weff[768x768] + bias
// Tiles: BM=32, BN=32, BK=32. 128 threads, each computes 2x4 outputs.
// Grid: (768/32) x (256/32) = 24 x 8 = 192 CTAs.
// ---------------------------------------------------------------------------
#define BM 32
#define BN 32
#define BK 32

__global__ __launch_bounds__(128)
void gemm_bias_kernel(const float* __restrict__ A,
                      const float* __restrict__ bias,
                      float*       __restrict__ C) {
    __shared__ float As[BK][BM + 1];   // A tile stored k-major (transposed)
    __shared__ float Bs[BK][BN];       // Weff tile, k rows, f contiguous

    const int tid = threadIdx.x;
    const int tx  = tid & 7;       // 0..7  -> 4 output features each
    const int ty  = tid >> 3;      // 0..15 -> 2 output rows each

    // global->shared load indices (float4 per load, 2 loads per operand)
    const int lr = tid >> 3;            // 0..15
    const int lc = (tid & 7) * 4;       // 0,4,...,28

    const float* Ab = A + blockIdx.y * BM * NX;
    const float* Bb = g_weff + blockIdx.x * BN;

    float acc[2][4];
#pragma unroll
    for (int i = 0; i < 2; i++)
#pragma unroll
        for (int j = 0; j < 4; j++) acc[i][j] = 0.0f;

    for (int k0 = 0; k0 < NX; k0 += BK) {
        // load A tile (32 rows x 32 k) transposed into As[k][b]
        float4 a0 = *(const float4*)(Ab + (lr     ) * NX + k0 + lc);
        float4 a1 = *(const float4*)(Ab + (lr + 16) * NX + k0 + lc);
        As[lc + 0][lr]      = a0.x;
        As[lc + 1][lr]      = a0.y;
        As[lc + 2][lr]      = a0.z;
        As[lc + 3][lr]      = a0.w;
        As[lc + 0][lr + 16] = a1.x;
        As[lc + 1][lr + 16] = a1.y;
        As[lc + 2][lr + 16] = a1.z;
        As[lc + 3][lr + 16] = a1.w;

        // load Weff tile (32 k-rows x 32 f)
        float4 b0 = *(const float4*)(Bb + (k0 + lr     ) * NF + lc);
        float4 b1 = *(const float4*)(Bb + (k0 + lr + 16) * NF + lc);
        *(float4*)&Bs[lr     ][lc] = b0;
        *(float4*)&Bs[lr + 16][lc] = b1;

        __syncthreads();

#pragma unroll
        for (int kk = 0; kk < BK; kk++) {
            float av0 = As[kk][ty * 2 + 0];
            float av1 = As[kk][ty * 2 + 1];
            float4 bv = *(const float4*)&Bs[kk][tx * 4];
            acc[0][0] += av0 * bv.x;
            acc[0][1] += av0 * bv.y;
            acc[0][2] += av0 * bv.z;
            acc[0][3] += av0 * bv.w;
            acc[1][0] += av1 * bv.x;
            acc[1][1] += av1 * bv.y;
            acc[1][2] += av1 * bv.z;
            acc[1][3] += av1 * bv.w;
        }
        __syncthreads();
    }

    // epilogue: add bias, store
    const int fb  = blockIdx.x * BN + tx * 4;
    const int b0r = blockIdx.y * BM + ty * 2;
    float4 bsv = *(const float4*)(bias + fb);

    float4 o0 = make_float4(acc[0][0] + bsv.x, acc[0][1] + bsv.y,
                            acc[0][2] + bsv.z, acc[0][3] + bsv.w);
    float4 o1 = make_float4(acc[1][0] + bsv.x, acc[1][1] + bsv.y,
                            acc[1][2] + bsv.z, acc[1][3] + bsv.w);
    *(float4*)(C + (b0r + 0) * NF + fb) = o0;
    *(float4*)(C + (b0r + 1) * NF + fb) = o1;
}

// ---------------------------------------------------------------------------
extern "C" void kernel_launch(void* const* d_in, const int* in_sizes, int n_in,
                              void* d_out, int out_size) {
    const float* x      = (const float*)d_in[0];
    const float* scale  = (const float*)d_in[1];
    const int*   binary = (const int*)  d_in[2];
    const float* bias   = (const float*)d_in[3];
    float*       out    = (float*)d_out;

    build_weff_kernel<<<(NG * NF + 255) / 256, 256>>>(scale, binary);

    dim3 grid(NF / BN, NBROWS / BM);   // 24 x 8 = 192 CTAs
    gemm_bias_kernel<<<grid, 128>>>(x, bias, out);
}

// round 2
// speedup vs baseline: 1.8142x; 1.8142x over previous
#include <cuda_runtime.h>

// Shapes (fixed):
//   x      : (4, 64, 768)  fp32   -> A [256 x 768]
//   scale  : (1, 8, 768)   fp32
//   binary : (1, 8, 96, 768) int32 (packed sign bytes)
//   bias   : (768,)        fp32
//   out    : (4, 64, 768)  fp32   -> C [256 x 768]
//
// out = x @ Weff + bias, Weff[8m+p, f] = sum_k scale[k,f]*sign(bit(7-p) of binary[k,m,f])

#define NX 768
#define NF 768
#define NM 256
#define BITS 8
#define NG 96

#define BM 64
#define BN 64
#define BK 16
#define SPLITS 8
#define KCHUNK (NX / SPLITS)   // 96

__device__ float g_weff[NX * NF];

// ---------------------------------------------------------------------------
// Kernel 1: fold 8 bit-planes * scale into fp32 weight matrix.
// ---------------------------------------------------------------------------
__global__ __launch_bounds__(256)
void build_weff_kernel(const float* __restrict__ scale,
                       const int*   __restrict__ binary) {
    int t = blockIdx.x * 256 + threadIdx.x;
    if (t >= NG * NF) return;
    int f = t % NF;
    int m = t / NF;

    float w[8];
#pragma unroll
    for (int p = 0; p < 8; p++) w[p] = 0.0f;

#pragma unroll
    for (int k = 0; k < BITS; k++) {
        int   c = binary[(k * NG + m) * NF + f];
        float s = scale[k * NF + f];
#pragma unroll
        for (int p = 0; p < 8; p++)
            w[p] += ((c >> (7 - p)) & 1) ? s : -s;
    }
#pragma unroll
    for (int p = 0; p < 8; p++)
        g_weff[(m * 8 + p) * NF + f] = w[p];
}

// ---------------------------------------------------------------------------
// Kernel 2: init out with broadcast bias (so split-K parts can red.add).
// 256x768 floats = 49152 float4.
// ---------------------------------------------------------------------------
__global__ __launch_bounds__(256)
void init_bias_kernel(const float* __restrict__ bias, float* __restrict__ out) {
    int idx = blockIdx.x * 256 + threadIdx.x;           // float4 index
    if (idx >= NM * NF / 4) return;
    const float4* b4 = (const float4*)bias;             // 192 float4
    ((float4*)out)[idx] = b4[idx % (NF / 4)];
}

// ---------------------------------------------------------------------------
// Kernel 3: split-K GEMM. Grid (NF/BN, NM/BM, SPLITS) = (12, 4, 8) = 384 CTAs.
// 256 threads, each computes a 4x4 output tile over K-chunk of 96.
// Partials merged with red.global.add.v4.f32.
// ---------------------------------------------------------------------------
__global__ __launch_bounds__(256)
void gemm_splitk_kernel(const float* __restrict__ A,
                        float*       __restrict__ C) {
    __shared__ float As[BK][BM + 4];   // k-major (transposed A tile), stride 68
    __shared__ float Bs[BK][BN];       // k rows, f contiguous

    const int tid = threadIdx.x;
    const int tx  = tid & 15;          // 0..15 -> 4 output features
    const int ty  = tid >> 4;          // 0..15 -> 4 output rows

    // loader indices
    const int ar = tid >> 2;           // 0..63  (A row within tile)
    const int ac = (tid & 3) * 4;      // 0,4,8,12 (k offset)
    const int br = tid >> 4;           // 0..15  (k row of B tile)
    const int bc = (tid & 15) * 4;     // 0..60  (f offset)

    const float* Ab = A + blockIdx.y * BM * NX;
    const float* Bb = g_weff + blockIdx.x * BN;
    const int k_base = blockIdx.z * KCHUNK;

    float acc[4][4];
#pragma unroll
    for (int i = 0; i < 4; i++)
#pragma unroll
        for (int j = 0; j < 4; j++) acc[i][j] = 0.0f;

#pragma unroll
    for (int kt = 0; kt < KCHUNK / BK; kt++) {
        const int k0 = k_base + kt * BK;

        float4 a = *(const float4*)(Ab + ar * NX + k0 + ac);
        float4 b = *(const float4*)(Bb + (k0 + br) * NF + bc);

        As[ac + 0][ar] = a.x;
        As[ac + 1][ar] = a.y;
        As[ac + 2][ar] = a.z;
        As[ac + 3][ar] = a.w;
        *(float4*)&Bs[br][bc] = b;

        __syncthreads();

#pragma unroll
        for (int kk = 0; kk < BK; kk++) {
            float4 av = *(const float4*)&As[kk][ty * 4];
            float4 bv = *(const float4*)&Bs[kk][tx * 4];
            acc[0][0] += av.x * bv.x; acc[0][1] += av.x * bv.y;
            acc[0][2] += av.x * bv.z; acc[0][3] += av.x * bv.w;
            acc[1][0] += av.y * bv.x; acc[1][1] += av.y * bv.y;
            acc[1][2] += av.y * bv.z; acc[1][3] += av.y * bv.w;
            acc[2][0] += av.z * bv.x; acc[2][1] += av.z * bv.y;
            acc[2][2] += av.z * bv.z; acc[2][3] += av.z * bv.w;
            acc[3][0] += av.w * bv.x; acc[3][1] += av.w * bv.y;
            acc[3][2] += av.w * bv.z; acc[3][3] += av.w * bv.w;
        }
        __syncthreads();
    }

    // merge partials into C (pre-initialized with bias)
    const int fb = blockIdx.x * BN + tx * 4;
    const int rb = blockIdx.y * BM + ty * 4;
#pragma unroll
    for (int i = 0; i < 4; i++) {
        float* p = C + (rb + i) * NF + fb;
        asm volatile("red.global.add.v4.f32 [%0], {%1, %2, %3, %4};"
                     :: "l"(p), "f"(acc[i][0]), "f"(acc[i][1]),
                        "f"(acc[i][2]), "f"(acc[i][3])
                     : "memory");
    }
}

// ---------------------------------------------------------------------------
extern "C" void kernel_launch(void* const* d_in, const int* in_sizes, int n_in,
                              void* d_out, int out_size) {
    const float* x      = (const float*)d_in[0];
    const float* scale  = (const float*)d_in[1];
    const int*   binary = (const int*)  d_in[2];
    const float* bias   = (const float*)d_in[3];
    float*       out    = (float*)d_out;

    build_weff_kernel<<<(NG * NF + 255) / 256, 256>>>(scale, binary);
    init_bias_kernel<<<(NM * NF / 4 + 255) / 256, 256>>>(bias, out);

    dim3 grid(NF / BN, NM / BM, SPLITS);   // 12 x 4 x 8 = 384 CTAs
    gemm_splitk_kernel<<<grid, 256>>>(x, out);
}

// round 4
// speedup vs baseline: 2.2633x; 1.2475x over previous
#include <cuda_runtime.h>
#include <cuda_bf16.h>
#include <cstdint>

// Shapes (fixed):
//   x (4,64,768) fp32 -> A[256x768]; scale (1,8,768); binary (1,8,96,768) int32;
//   bias (768,); out (4,64,768) fp32 -> C[256x768]
// out = x @ Weff + bias, Weff[8m+p, f] = sum_k scale[k,f]*sign(bit(7-p) of binary[k,m,f])
//
// Split-bf16 tensor-core path (portable sm_100 HMMA, no tcgen05):
//   Ah/Al = bf16 hi/lo split of x; Bh/Bl = bf16 hi/lo split of Weff^T ([f][k])
//   out = Ah*Bh + Al*Bh + Ah*Bl  (3 segments, mma.sync m16n8k16, fp32 accum)

#define NX 768
#define NF 768
#define NM 256
#define NG 96

__device__ __nv_bfloat16 g_ah[NM * NX];
__device__ __nv_bfloat16 g_al[NM * NX];
__device__ __nv_bfloat16 g_bh[NF * NX];   // [f][k]
__device__ __nv_bfloat16 g_bl[NF * NX];

// ---------------------------------------------------------------------------
union B2U { __nv_bfloat162 h2; uint32_t u; };
__device__ __forceinline__ uint32_t pk2(__nv_bfloat16 a, __nv_bfloat16 b) {
    B2U t; t.h2 = __halves2bfloat162(a, b); return t.u;
}
__device__ __forceinline__ uint32_t smem_u32(const void* p) {
    uint32_t a;
    asm("{ .reg .u64 t; cvta.to.shared.u64 t, %1; cvt.u32.u64 %0, t; }"
        : "=r"(a) : "l"(p));
    return a;
}
__device__ __forceinline__ void cp16(uint32_t s, const void* g) {
    asm volatile("cp.async.cg.shared.global [%0], [%1], 16;" :: "r"(s), "l"(g));
}
#define CP_COMMIT() asm volatile("cp.async.commit_group;" ::: "memory")

#define LDSM4(r, addr) \
    asm volatile("ldmatrix.sync.aligned.m8n8.x4.shared.b16 {%0,%1,%2,%3}, [%4];" \
                 : "=r"((r)[0]), "=r"((r)[1]), "=r"((r)[2]), "=r"((r)[3]) : "r"(addr))

#define MMA16816(c, a, bb0, bb1) \
    asm volatile("mma.sync.aligned.m16n8k16.row.col.f32.bf16.bf16.f32 " \
                 "{%0,%1,%2,%3}, {%4,%5,%6,%7}, {%8,%9}, {%0,%1,%2,%3};" \
                 : "+f"((c)[0]), "+f"((c)[1]), "+f"((c)[2]), "+f"((c)[3]) \
                 : "r"((a)[0]), "r"((a)[1]), "r"((a)[2]), "r"((a)[3]), \
                   "r"(bb0), "r"(bb1))

// ---------------------------------------------------------------------------
// Kernel 1 (fused prep): blocks [0,288) build Bh/Bl; [288,480) split x;
// [480,672) seed out with bias.
// ---------------------------------------------------------------------------
__global__ __launch_bounds__(256)
void prep_kernel(const float* __restrict__ scale,
                 const int*   __restrict__ binary,
                 const float* __restrict__ x,
                 const float* __restrict__ bias,
                 float*       __restrict__ out) {
    const int b = blockIdx.x, tid = threadIdx.x;

    if (b < 288) {                       // ---- build Weff -> bf16 hi/lo ----
        const int t = b * 256 + tid;     // t < 73728 = NG*NF exactly
        const int f = t % NF;            // coalesced
        const int m = t / NF;

        int   c[8];
        float s[8];
#pragma unroll
        for (int k = 0; k < 8; k++) {
            c[k] = binary[(k * NG + m) * NF + f];
            s[k] = scale[k * NF + f];
        }
        float w[8];
#pragma unroll
        for (int p = 0; p < 8; p++) w[p] = 0.0f;
#pragma unroll
        for (int k = 0; k < 8; k++)
#pragma unroll
            for (int p = 0; p < 8; p++)
                w[p] += ((c[k] >> (7 - p)) & 1) ? s[k] : -s[k];

        __nv_bfloat16 hi[8], lo[8];
#pragma unroll
        for (int p = 0; p < 8; p++) {
            hi[p] = __float2bfloat16(w[p]);
            lo[p] = __float2bfloat16(w[p] - __bfloat162float(hi[p]));
        }
        *(uint4*)(g_bh + (size_t)f * NX + 8 * m) =
            make_uint4(pk2(hi[0], hi[1]), pk2(hi[2], hi[3]),
                       pk2(hi[4], hi[5]), pk2(hi[6], hi[7]));
        *(uint4*)(g_bl + (size_t)f * NX + 8 * m) =
            make_uint4(pk2(lo[0], lo[1]), pk2(lo[2], lo[3]),
                       pk2(lo[4], lo[5]), pk2(lo[6], lo[7]));
    } else if (b < 480) {                // ---- split x -> Ah/Al ----
        const int i = (b - 288) * 256 + tid;   // < 49152 = NM*NX/4 exactly
        float4 v = ((const float4*)x)[i];
        __nv_bfloat16 h0 = __float2bfloat16(v.x), h1 = __float2bfloat16(v.y);
        __nv_bfloat16 h2 = __float2bfloat16(v.z), h3 = __float2bfloat16(v.w);
        __nv_bfloat16 l0 = __float2bfloat16(v.x - __bfloat162float(h0));
        __nv_bfloat16 l1 = __float2bfloat16(v.y - __bfloat162float(h1));
        __nv_bfloat16 l2 = __float2bfloat16(v.z - __bfloat162float(h2));
        __nv_bfloat16 l3 = __float2bfloat16(v.w - __bfloat162float(h3));
        ((uint2*)g_ah)[i] = make_uint2(pk2(h0, h1), pk2(h2, h3));
        ((uint2*)g_al)[i] = make_uint2(pk2(l0, l1), pk2(l2, l3));
    } else {                             // ---- seed out with bias ----
        const int idx = (b - 480) * 256 + tid; // < 49152 = NM*NF/4 exactly
        ((float4*)out)[idx] = ((const float4*)bias)[idx % (NF / 4)];
    }
}

// ---------------------------------------------------------------------------
// Kernel 2: HMMA GEMM. Grid (12 n, 4 m, 3 seg) = 144 CTAs x 128 thr.
// BM=BN=BK=64, double-buffered cp.async, 4 warps each 32x32.
// ---------------------------------------------------------------------------
#define BK 64
#define ROWP 72   // 64 + 8 halves padding (144 B rows, conflict-free ldmatrix)

__global__ __launch_bounds__(128)
void gemm_mma_kernel(float* __restrict__ C) {
    __shared__ __align__(16) __nv_bfloat16 As[2][64][ROWP];
    __shared__ __align__(16) __nv_bfloat16 Bs[2][64][ROWP];

    const int tid  = threadIdx.x;
    const int wid  = tid >> 5;
    const int lane = tid & 31;

    const int f0 = blockIdx.x * 64;
    const int m0 = blockIdx.y * 64;
    const int sg = blockIdx.z;

    const __nv_bfloat16* Ag = ((sg == 1) ? g_al : g_ah) + (size_t)m0 * NX;
    const __nv_bfloat16* Bg = ((sg == 2) ? g_bl : g_bh) + (size_t)f0 * NX;

    const int wm = (wid >> 1) * 32;   // warp m offset
    const int wn = (wid & 1) * 32;    // warp n offset

    float acc[2][4][4];
#pragma unroll
    for (int i = 0; i < 2; i++)
#pragma unroll
        for (int j = 0; j < 4; j++)
#pragma unroll
            for (int v = 0; v < 4; v++) acc[i][j][v] = 0.0f;

    auto load = [&](int ci, int bu) {
        const __nv_bfloat16* a = Ag + ci * BK;
        const __nv_bfloat16* bb = Bg + ci * BK;
#pragma unroll
        for (int j = 0; j < 4; j++) {
            int idx = tid + 128 * j;          // 0..511
            int r = idx >> 3, c8 = (idx & 7) * 8;
            cp16(smem_u32(&As[bu][r][c8]), a + (size_t)r * NX + c8);
            cp16(smem_u32(&Bs[bu][r][c8]), bb + (size_t)r * NX + c8);
        }
        CP_COMMIT();
    };

    load(0, 0);

    for (int i = 0; i < NX / BK; i++) {       // 12 chunks
        if (i + 1 < NX / BK) {
            load(i + 1, (i + 1) & 1);
            asm volatile("cp.async.wait_group 1;" ::: "memory");
        } else {
            asm volatile("cp.async.wait_group 0;" ::: "memory");
        }
        __syncthreads();

        const int bu = i & 1;
#pragma unroll
        for (int ks = 0; ks < 4; ks++) {
            const int k0 = ks * 16;
            const int c  = k0 + ((lane >> 4) << 3);   // 8-col group per half-warp
            uint32_t a0[4], a1[4], b0[4], b1[4];
            {
                int r = wm + (lane & 15);
                LDSM4(a0, smem_u32(&As[bu][r][c]));
                LDSM4(a1, smem_u32(&As[bu][r + 16][c]));
            }
            {
                int r = wn + (lane & 15);
                LDSM4(b0, smem_u32(&Bs[bu][r][c]));
                LDSM4(b1, smem_u32(&Bs[bu][r + 16][c]));
            }
            // b0: mat0=n0..7@k0, mat1=n8..15@k0, mat2=n0..7@k8, mat3=n8..15@k8
            MMA16816(acc[0][0], a0, b0[0], b0[2]);
            MMA16816(acc[0][1], a0, b0[1], b0[3]);
            MMA16816(acc[0][2], a0, b1[0], b1[2]);
            MMA16816(acc[0][3], a0, b1[1], b1[3]);
            MMA16816(acc[1][0], a1, b0[0], b0[2]);
            MMA16816(acc[1][1], a1, b0[1], b0[3]);
            MMA16816(acc[1][2], a1, b1[0], b1[2]);
            MMA16816(acc[1][3], a1, b1[1], b1[3]);
        }
        __syncthreads();
    }

    // epilogue: red.add partial sums into bias-seeded C
    const int rbase = m0 + wm + (lane >> 2);
    const int cbase = f0 + wn + (lane & 3) * 2;
#pragma unroll
    for (int mi = 0; mi < 2; mi++) {
#pragma unroll
        for (int ni = 0; ni < 4; ni++) {
            int row = rbase + mi * 16;
            int col = cbase + ni * 8;
            float* p0 = C + (size_t)row * NF + col;
            float* p1 = C + (size_t)(row + 8) * NF + col;
            asm volatile("red.global.add.v2.f32 [%0], {%1, %2};"
                         :: "l"(p0), "f"(acc[mi][ni][0]), "f"(acc[mi][ni][1]) : "memory");
            asm volatile("red.global.add.v2.f32 [%0], {%1, %2};"
                         :: "l"(p1), "f"(acc[mi][ni][2]), "f"(acc[mi][ni][3]) : "memory");
        }
    }
}

// ---------------------------------------------------------------------------
extern "C" void kernel_launch(void* const* d_in, const int* in_sizes, int n_in,
                              void* d_out, int out_size) {
    const float* x      = (const float*)d_in[0];
    const float* scale  = (const float*)d_in[1];
    const int*   binary = (const int*)  d_in[2];
    const float* bias   = (const float*)d_in[3];
    float*       out    = (float*)d_out;

    prep_kernel<<<672, 256>>>(scale, binary, x, bias, out);

    dim3 grid(NF / 64, NM / 64, 3);   // 12 x 4 x 3 = 144 CTAs
    gemm_mma_kernel<<<grid, 128>>>(out);
}

// round 5
// speedup vs baseline: 2.4563x; 1.0853x over previous
#include <cuda_runtime.h>
#include <cuda_bf16.h>
#include <cstdint>

// out = x @ Weff + bias;  Weff[8m+p, f] = sum_k scale[k,f]*sign(bit(7-p) of binary[k,m,f])
// Split-bf16 HMMA path: out = Ah*Bh + Al*Bh + Ah*Bl (fused accumulator),
// split-K=6 with STG partials + reduce (no atomics).

#define NX 768
#define NF 768
#define NM 256
#define NG 96

#define SPLITS 6
#define BKC 128          // k per CTA = NX / SPLITS
#define ROWP 136         // 128 + 8 halves pad (272B rows, 17x16B -> conflict-free ldmatrix)

__device__ __nv_bfloat16 g_ah[NM * NX];
__device__ __nv_bfloat16 g_al[NM * NX];
__device__ __nv_bfloat16 g_bh[NF * NX];   // [f][k]
__device__ __nv_bfloat16 g_bl[NF * NX];
__device__ float g_part[SPLITS * NM * NF];

// ---------------------------------------------------------------------------
union B2U { __nv_bfloat162 h2; uint32_t u; };
__device__ __forceinline__ uint32_t pk2(__nv_bfloat16 a, __nv_bfloat16 b) {
    B2U t; t.h2 = __halves2bfloat162(a, b); return t.u;
}
__device__ __forceinline__ uint32_t smem_u32(const void* p) {
    uint32_t a;
    asm("{ .reg .u64 t; cvta.to.shared.u64 t, %1; cvt.u32.u64 %0, t; }"
        : "=r"(a) : "l"(p));
    return a;
}
__device__ __forceinline__ void cp16(uint32_t s, const void* g) {
    asm volatile("cp.async.cg.shared.global [%0], [%1], 16;" :: "r"(s), "l"(g));
}

#define LDSM4(r, addr) \
    asm volatile("ldmatrix.sync.aligned.m8n8.x4.shared.b16 {%0,%1,%2,%3}, [%4];" \
                 : "=r"((r)[0]), "=r"((r)[1]), "=r"((r)[2]), "=r"((r)[3]) : "r"(addr))

#define MMA16816(c, a, bb0, bb1) \
    asm volatile("mma.sync.aligned.m16n8k16.row.col.f32.bf16.bf16.f32 " \
                 "{%0,%1,%2,%3}, {%4,%5,%6,%7}, {%8,%9}, {%0,%1,%2,%3};" \
                 : "+f"((c)[0]), "+f"((c)[1]), "+f"((c)[2]), "+f"((c)[3]) \
                 : "r"((a)[0]), "r"((a)[1]), "r"((a)[2]), "r"((a)[3]), \
                   "r"(bb0), "r"(bb1))

// ---------------------------------------------------------------------------
// Kernel 1 (fused prep): blocks [0,288) build Bh/Bl from binary*scale;
// blocks [288,480) split x into Ah/Al.
// ---------------------------------------------------------------------------
__global__ __launch_bounds__(256)
void prep_kernel(const float* __restrict__ scale,
                 const int*   __restrict__ binary,
                 const float* __restrict__ x) {
    const int b = blockIdx.x, tid = threadIdx.x;

    if (b < 288) {
        const int t = b * 256 + tid;     // < 73728 = NG*NF
        const int f = t % NF;
        const int m = t / NF;

        int   c[8];
        float s[8];
#pragma unroll
        for (int k = 0; k < 8; k++) {
            c[k] = binary[(k * NG + m) * NF + f];
            s[k] = scale[k * NF + f];
        }
        float w[8];
#pragma unroll
        for (int p = 0; p < 8; p++) w[p] = 0.0f;
#pragma unroll
        for (int k = 0; k < 8; k++)
#pragma unroll
            for (int p = 0; p < 8; p++)
                w[p] += ((c[k] >> (7 - p)) & 1) ? s[k] : -s[k];

        __nv_bfloat16 hi[8], lo[8];
#pragma unroll
        for (int p = 0; p < 8; p++) {
            hi[p] = __float2bfloat16(w[p]);
            lo[p] = __float2bfloat16(w[p] - __bfloat162float(hi[p]));
        }
        *(uint4*)(g_bh + (size_t)f * NX + 8 * m) =
            make_uint4(pk2(hi[0], hi[1]), pk2(hi[2], hi[3]),
                       pk2(hi[4], hi[5]), pk2(hi[6], hi[7]));
        *(uint4*)(g_bl + (size_t)f * NX + 8 * m) =
            make_uint4(pk2(lo[0], lo[1]), pk2(lo[2], lo[3]),
                       pk2(lo[4], lo[5]), pk2(lo[6], lo[7]));
    } else {
        const int i = (b - 288) * 256 + tid;   // < 49152 = NM*NX/4
        float4 v = ((const float4*)x)[i];
        __nv_bfloat16 h0 = __float2bfloat16(v.x), h1 = __float2bfloat16(v.y);
        __nv_bfloat16 h2 = __float2bfloat16(v.z), h3 = __float2bfloat16(v.w);
        __nv_bfloat16 l0 = __float2bfloat16(v.x - __bfloat162float(h0));
        __nv_bfloat16 l1 = __float2bfloat16(v.y - __bfloat162float(h1));
        __nv_bfloat16 l2 = __float2bfloat16(v.z - __bfloat162float(h2));
        __nv_bfloat16 l3 = __float2bfloat16(v.w - __bfloat162float(h3));
        ((uint2*)g_ah)[i] = make_uint2(pk2(h0, h1), pk2(h2, h3));
        ((uint2*)g_al)[i] = make_uint2(pk2(l0, l1), pk2(l2, l3));
    }
}

// ---------------------------------------------------------------------------
// Kernel 2: fused-segment HMMA GEMM, split-K partials.
// Grid (12 n, 4 m, 6 split) = 288 CTAs x 256 thr (8 warps, warp tile 16x32).
// Each CTA: k-chunk of 128; loads Ah/Al/Bh/Bl tiles (64x128 each) once.
// ---------------------------------------------------------------------------
#define SM_T (64 * ROWP)             // halves per tile
#define SMEM_BYTES (4 * SM_T * 2)    // 69632

__global__ __launch_bounds__(256)
void gemm_mma_kernel() {
    extern __shared__ __align__(16) __nv_bfloat16 sm[];
    __nv_bfloat16* AH = sm;
    __nv_bfloat16* AL = sm + SM_T;
    __nv_bfloat16* BH = sm + 2 * SM_T;
    __nv_bfloat16* BL = sm + 3 * SM_T;

    const int tid  = threadIdx.x;
    const int wid  = tid >> 5;
    const int lane = tid & 31;

    const int f0 = blockIdx.x * 64;
    const int m0 = blockIdx.y * 64;
    const int k0 = blockIdx.z * BKC;

    const __nv_bfloat16* gAH = g_ah + (size_t)m0 * NX + k0;
    const __nv_bfloat16* gAL = g_al + (size_t)m0 * NX + k0;
    const __nv_bfloat16* gBH = g_bh + (size_t)f0 * NX + k0;
    const __nv_bfloat16* gBL = g_bl + (size_t)f0 * NX + k0;

    // load all four 64x128 tiles (16 cp.async x 16B per thread)
#pragma unroll
    for (int j = 0; j < 4; j++) {
        int idx = tid + 256 * j;         // 0..1023
        int r = idx >> 4, c8 = (idx & 15) * 8;
        size_t go = (size_t)r * NX + c8;
        uint32_t so = smem_u32(sm) + (uint32_t)(r * ROWP + c8) * 2;
        cp16(so,                   gAH + go);
        cp16(so + SM_T * 2,        gAL + go);
        cp16(so + 2 * SM_T * 2,    gBH + go);
        cp16(so + 3 * SM_T * 2,    gBL + go);
    }
    asm volatile("cp.async.commit_group;" ::: "memory");

    const int wm = (wid >> 1) * 16;   // 4 warps along m
    const int wn = (wid & 1) * 32;    // 2 warps along n

    float acc[4][4];
#pragma unroll
    for (int j = 0; j < 4; j++)
#pragma unroll
        for (int v = 0; v < 4; v++) acc[j][v] = 0.0f;

    asm volatile("cp.async.wait_group 0;" ::: "memory");
    __syncthreads();

    const int ra  = wm + (lane & 15);
    const int rb0 = wn + (lane & 15);
    const uint32_t smb = smem_u32(sm);

#pragma unroll
    for (int ks = 0; ks < 8; ks++) {
        const int c = ks * 16 + ((lane >> 4) << 3);
        uint32_t ah[4], al[4], bh0[4], bh1[4], bl0[4], bl1[4];
        LDSM4(ah,  smb + (uint32_t)(ra * ROWP + c) * 2);
        LDSM4(al,  smb + (uint32_t)(SM_T + ra * ROWP + c) * 2);
        LDSM4(bh0, smb + (uint32_t)(2 * SM_T + rb0 * ROWP + c) * 2);
        LDSM4(bh1, smb + (uint32_t)(2 * SM_T + (rb0 + 16) * ROWP + c) * 2);
        LDSM4(bl0, smb + (uint32_t)(3 * SM_T + rb0 * ROWP + c) * 2);
        LDSM4(bl1, smb + (uint32_t)(3 * SM_T + (rb0 + 16) * ROWP + c) * 2);

        // Ah*Bh
        MMA16816(acc[0], ah, bh0[0], bh0[2]);
        MMA16816(acc[1], ah, bh0[1], bh0[3]);
        MMA16816(acc[2], ah, bh1[0], bh1[2]);
        MMA16816(acc[3], ah, bh1[1], bh1[3]);
        // Al*Bh
        MMA16816(acc[0], al, bh0[0], bh0[2]);
        MMA16816(acc[1], al, bh0[1], bh0[3]);
        MMA16816(acc[2], al, bh1[0], bh1[2]);
        MMA16816(acc[3], al, bh1[1], bh1[3]);
        // Ah*Bl
        MMA16816(acc[0], ah, bl0[0], bl0[2]);
        MMA16816(acc[1], ah, bl0[1], bl0[3]);
        MMA16816(acc[2], ah, bl1[0], bl1[2]);
        MMA16816(acc[3], ah, bl1[1], bl1[3]);
    }

    // store partials (plain STG.64, no atomics)
    float* P = g_part + (size_t)blockIdx.z * (NM * NF);
    const int rbase = m0 + wm + (lane >> 2);
    const int cbase = f0 + wn + (lane & 3) * 2;
#pragma unroll
    for (int ni = 0; ni < 4; ni++) {
        int col = cbase + ni * 8;
        *(float2*)(P + (size_t)rbase * NF + col)       = make_float2(acc[ni][0], acc[ni][1]);
        *(float2*)(P + (size_t)(rbase + 8) * NF + col) = make_float2(acc[ni][2], acc[ni][3]);
    }
}

// ---------------------------------------------------------------------------
// Kernel 3: reduce 6 partials + bias -> out. 49152 float4 threads.
// ---------------------------------------------------------------------------
__global__ __launch_bounds__(256)
void reduce_kernel(const float* __restrict__ bias, float* __restrict__ out) {
    const int idx = blockIdx.x * 256 + threadIdx.x;   // < NM*NF/4
    float4 p[SPLITS];
#pragma unroll
    for (int s = 0; s < SPLITS; s++)
        p[s] = ((const float4*)g_part)[s * (NM * NF / 4) + idx];
    float4 v = ((const float4*)bias)[idx % (NF / 4)];
#pragma unroll
    for (int s = 0; s < SPLITS; s++) {
        v.x += p[s].x; v.y += p[s].y; v.z += p[s].z; v.w += p[s].w;
    }
    ((float4*)out)[idx] = v;
}

// ---------------------------------------------------------------------------
extern "C" void kernel_launch(void* const* d_in, const int* in_sizes, int n_in,
                              void* d_out, int out_size) {
    const float* x      = (const float*)d_in[0];
    const float* scale  = (const float*)d_in[1];
    const int*   binary = (const int*)  d_in[2];
    const float* bias   = (const float*)d_in[3];
    float*       out    = (float*)d_out;

    static bool attr_set = false;
    if (!attr_set) {
        cudaFuncSetAttribute(gemm_mma_kernel,
                             cudaFuncAttributeMaxDynamicSharedMemorySize, SMEM_BYTES);
        attr_set = true;
    }

    prep_kernel<<<480, 256>>>(scale, binary, x);

    dim3 grid(NF / 64, NM / 64, SPLITS);   // 12 x 4 x 6 = 288 CTAs
    gemm_mma_kernel<<<grid, 256, SMEM_BYTES>>>();

    reduce_kernel<<<NM * NF / 4 / 256, 256>>>(bias, out);
}